// round 1
// baseline (speedup 1.0000x reference)
#include <cuda_runtime.h>
#include <cstdint>

#define N_IMG 64
#define CIN   128
#define COUT  128
#define HH    56
#define WW    56
#define HW    (HH*WW)      /* 3136 */
#define HP    58
#define WP    58
#define PHW   (HP*WP)      /* 3364 */

// Padded packed sign bits of activation: [n][hp][wp] -> uint4 (128 channels, bit=1 means +1)
__device__ uint4 g_px[N_IMG * PHW];          // 64*3364*16B = 3.44 MB
// Packed sign bits of weights: [o][tap] -> uint4
__device__ uint4 g_pw[COUT * 9];
// Per-channel scale*BN factor
__device__ float g_A[COUT];
// Border-type-folded bias: [type 0..8][o]
__device__ float g_Bc[9 * COUT];

// ---------------------------------------------------------------------------
// Kernel 0: zero the padded packed array (border cells must be 0 every call)
// ---------------------------------------------------------------------------
__global__ void zero_px_kernel() {
    int i = blockIdx.x * 256 + threadIdx.x;
    if (i < N_IMG * PHW) g_px[i] = make_uint4(0u, 0u, 0u, 0u);
}

// ---------------------------------------------------------------------------
// Kernel 1: pack sign(x) bits. One thread per pixel; coalesced channel loop.
// ---------------------------------------------------------------------------
__global__ void pack_x_kernel(const float* __restrict__ x) {
    int p = blockIdx.x * 256 + threadIdx.x;          // 0 .. 200703
    if (p >= N_IMG * HW) return;
    int n  = p / HW;
    int hw = p - n * HW;
    const float* xp = x + (size_t)n * CIN * HW + hw;

    uint32_t w0 = 0u, w1 = 0u, w2 = 0u, w3 = 0u;
#pragma unroll 8
    for (int c = 0; c < 32; c++) {
        // bit = 1 iff value >= +0 (sign bit clear)  -> treated as +1
        w0 |= ((__float_as_uint(xp[(size_t)(c      ) * HW]) >> 31) ^ 1u) << c;
        w1 |= ((__float_as_uint(xp[(size_t)(c + 32 ) * HW]) >> 31) ^ 1u) << c;
        w2 |= ((__float_as_uint(xp[(size_t)(c + 64 ) * HW]) >> 31) ^ 1u) << c;
        w3 |= ((__float_as_uint(xp[(size_t)(c + 96 ) * HW]) >> 31) ^ 1u) << c;
    }
    int h = hw / WW, w = hw - (hw / WW) * WW;
    g_px[n * PHW + (h + 1) * WP + (w + 1)] = make_uint4(w0, w1, w2, w3);
}

// ---------------------------------------------------------------------------
// Kernel 2: weight prep. One block (128 threads) per output channel.
//   scale_o = mean|w|, packed sign bits, per-tap popcounts, and
//   Bc[type][o] = (beta - mean*inv) - A_o * sum_{invalid taps}(128 - 2*wpop)
// ---------------------------------------------------------------------------
__global__ void prep_w_kernel(const float* __restrict__ wgt,
                              const float* __restrict__ gamma,
                              const float* __restrict__ beta,
                              const float* __restrict__ bn_mean,
                              const float* __restrict__ bn_var) {
    int o   = blockIdx.x;
    int tid = threadIdx.x;                      // 128 threads
    __shared__ float s_red[128];
    __shared__ int   s_wpop[9];
    __shared__ float sA, sBb;

    const float* wo = wgt + (size_t)o * CIN * 9;

    // |w| partial sums: thread tid owns input channel tid (9 contiguous taps)
    float s = 0.f;
#pragma unroll
    for (int t = 0; t < 9; t++) s += fabsf(wo[tid * 9 + t]);
    s_red[tid] = s;
    __syncthreads();
    for (int k = 64; k > 0; k >>= 1) {
        if (tid < k) s_red[tid] += s_red[tid + k];
        __syncthreads();
    }

    // Pack weight signs: thread t (<9) builds the 4 words of tap t
    if (tid < 9) {
        int t = tid;
        uint32_t wd[4] = {0u, 0u, 0u, 0u};
        for (int c = 0; c < CIN; c++) {
            uint32_t b = ((__float_as_uint(wo[(size_t)c * 9 + t]) >> 31) ^ 1u) & 1u;
            wd[c >> 5] |= b << (c & 31);
        }
        g_pw[o * 9 + t] = make_uint4(wd[0], wd[1], wd[2], wd[3]);
        s_wpop[t] = __popc(wd[0]) + __popc(wd[1]) + __popc(wd[2]) + __popc(wd[3]);
    }
    if (tid == 0) {
        float scale = s_red[0] * (1.0f / 1152.0f);
        float inv   = gamma[o] * rsqrtf(bn_var[o] + 1e-5f);
        sA  = scale * inv;
        sBb = beta[o] - bn_mean[o] * inv;
        g_A[o] = sA;
    }
    __syncthreads();

    // Border-type bias fold: type = rowtype*3 + coltype
    if (tid < 9) {
        int type = tid;
        int rt = type / 3, ct = type - rt * 3;
        int corr = 0;
#pragma unroll
        for (int t = 0; t < 9; t++) {
            int dh = t / 3, dw = t - dh * 3;
            bool inval = (rt == 0 && dh == 0) || (rt == 2 && dh == 2) ||
                         (ct == 0 && dw == 0) || (ct == 2 && dw == 2);
            if (inval) corr += 128 - 2 * s_wpop[t];
        }
        g_Bc[type * COUT + o] = sBb - sA * (float)corr;
    }
}

// ---------------------------------------------------------------------------
// Kernel 3: XNOR-popcount conv + BN + residual. One thread per output pixel,
// looping over all 128 output channels (weights cached in smem).
// ---------------------------------------------------------------------------
__global__ __launch_bounds__(256) void conv_kernel(const float* __restrict__ x,
                                                   float* __restrict__ out) {
    __shared__ uint4 s_w[COUT * 9];      // 18 KB packed weights
    __shared__ float s_A[COUT];
    __shared__ float s_Bc[9 * COUT];     // 4.5 KB

    int tid = threadIdx.x;
    for (int i = tid; i < COUT * 9; i += 256) s_w[i] = g_pw[i];
    for (int i = tid; i < COUT;     i += 256) s_A[i] = g_A[i];
    for (int i = tid; i < 9 * COUT; i += 256) s_Bc[i] = g_Bc[i];
    __syncthreads();

    int p = blockIdx.x * 256 + tid;          // 0 .. 200703 (grid sized exactly)
    int n  = p / HW;
    int hw = p - n * HW;
    int h = hw / WW, w = hw - (hw / WW) * WW;

    // 3x3 neighborhood of packed activations (zero-padded)
    const uint4* pxn = g_px + n * PHW + h * WP + w;   // == padded (h+dh, w+dw) base with +0 offset
    uint4 nb[9];
#pragma unroll
    for (int dh = 0; dh < 3; dh++)
#pragma unroll
        for (int dw = 0; dw < 3; dw++)
            nb[dh * 3 + dw] = pxn[dh * WP + dw];

    int rt = (h == 0) ? 0 : ((h == HH - 1) ? 2 : 1);
    int ct = (w == 0) ? 0 : ((w == WW - 1) ? 2 : 1);
    const float* bc = s_Bc + (rt * 3 + ct) * COUT;

    const float* xr   = x   + (size_t)n * CIN * HW + hw;
    float*       outr = out + (size_t)n * CIN * HW + hw;

#pragma unroll 4
    for (int o = 0; o < COUT; o++) {
        const uint4* wo = s_w + o * 9;
        int acc = 0;
#pragma unroll
        for (int t = 0; t < 9; t++) {
            uint4 wv = wo[t];
            uint4 av = nb[t];
            acc += __popc(av.x ^ wv.x) + __popc(av.y ^ wv.y)
                 + __popc(av.z ^ wv.z) + __popc(av.w ^ wv.w);
        }
        float dot = (float)(1152 - 2 * acc);
        float r = fmaf(s_A[o], dot, bc[o]) + xr[(size_t)o * HW];
        outr[(size_t)o * HW] = r;
    }
}

// ---------------------------------------------------------------------------
extern "C" void kernel_launch(void* const* d_in, const int* in_sizes, int n_in,
                              void* d_out, int out_size) {
    const float* x       = (const float*)d_in[0];
    const float* weight  = (const float*)d_in[1];
    const float* gamma   = (const float*)d_in[2];
    const float* beta    = (const float*)d_in[3];
    const float* bn_mean = (const float*)d_in[4];
    const float* bn_var  = (const float*)d_in[5];
    float* out = (float*)d_out;

    (void)in_sizes; (void)n_in; (void)out_size;

    // 64*3364 = 215296 uint4 cells -> 841 blocks * 256
    zero_px_kernel<<<841, 256>>>();
    // 200704 pixels -> 784 blocks * 256
    pack_x_kernel<<<784, 256>>>(x);
    prep_w_kernel<<<COUT, 128>>>(weight, gamma, beta, bn_mean, bn_var);
    conv_kernel<<<784, 256>>>(x, out);
}